// round 2
// baseline (speedup 1.0000x reference)
#include <cuda_runtime.h>
#include <math.h>

#define B_    8
#define N_    1024
#define D_    1024
#define H_    16
#define DH_   64
#define MLP_  4096
#define TOK   (B_ * N_)         // 8192 rows

// ---------------- scratch (no allocations allowed) ----------------
__device__ float g_xn  [TOK * D_];        // 32 MB
__device__ float g_qkv [TOK * 3 * D_];    // 96 MB
__device__ float g_attn[TOK * D_];        // 32 MB
__device__ float g_x2  [TOK * D_];        // 32 MB
__device__ float g_x2n [TOK * D_];        // 32 MB
__device__ float g_h   [TOK * MLP_];      // 128 MB

// ==================================================================
// LayerNorm: one block per row, D = 1024, 256 threads x float4
// ==================================================================
__global__ __launch_bounds__(256) void ln_kernel(
    const float* __restrict__ x, const float* __restrict__ g,
    const float* __restrict__ b, float* __restrict__ y)
{
    const int row  = blockIdx.x;
    const int tid  = threadIdx.x;
    const int lane = tid & 31, w = tid >> 5;
    const float* xr = x + (size_t)row * D_;

    float4 v = *(const float4*)(xr + tid * 4);
    float s  = v.x + v.y + v.z + v.w;
    float ss = fmaf(v.x, v.x, fmaf(v.y, v.y, fmaf(v.z, v.z, v.w * v.w)));
#pragma unroll
    for (int o = 16; o; o >>= 1) {
        s  += __shfl_xor_sync(0xffffffffu, s,  o);
        ss += __shfl_xor_sync(0xffffffffu, ss, o);
    }
    __shared__ float rs_[8], rss_[8];
    if (!lane) { rs_[w] = s; rss_[w] = ss; }
    __syncthreads();
    float S = 0.f, SS = 0.f;
#pragma unroll
    for (int i = 0; i < 8; ++i) { S += rs_[i]; SS += rss_[i]; }
    const float mu  = S * (1.0f / D_);
    const float var = SS * (1.0f / D_) - mu * mu;
    const float rstd = rsqrtf(var + 1e-5f);

    float4 gv = *(const float4*)(g + tid * 4);
    float4 bv = *(const float4*)(b + tid * 4);
    float4 o;
    o.x = (v.x - mu) * rstd * gv.x + bv.x;
    o.y = (v.y - mu) * rstd * gv.y + bv.y;
    o.z = (v.z - mu) * rstd * gv.z + bv.z;
    o.w = (v.w - mu) * rstd * gv.w + bv.w;
    *(float4*)(y + (size_t)row * D_ + tid * 4) = o;
}

// ==================================================================
// SGEMM: C[M,N] = A[M,K] @ B[K,N] (+bias)(+exact GELU)
// 128x128 tile, BK=16, 256 threads, 8x8 microtile (2x contiguous 4s)
// All dims are multiples of 128/16 in this problem: no bounds checks.
// ==================================================================
__device__ __forceinline__ float gelu_exact(float v)
{
    return 0.5f * v * (1.0f + erff(v * 0.70710678118654752f));
}

template <bool BIAS, bool GELU>
__global__ __launch_bounds__(256, 2) void sgemm_kernel(
    const float* __restrict__ A, const float* __restrict__ B,
    const float* __restrict__ bias, float* __restrict__ C,
    int M, int N, int K)
{
    const int bm = blockIdx.y * 128;
    const int bn = blockIdx.x * 128;
    const int tid = threadIdx.x;
    const int tx = tid & 15, ty = tid >> 4;

    __shared__ float As[16][132];   // transposed A tile, padded (2-way max on store)
    __shared__ float Bs[16][128];

    float acc[8][8];
#pragma unroll
    for (int i = 0; i < 8; ++i)
#pragma unroll
        for (int j = 0; j < 8; ++j) acc[i][j] = 0.f;

    const float* Aptr = A + (size_t)bm * K;
    const float* Bptr = B + bn;

    for (int k0 = 0; k0 < K; k0 += 16) {
        // A tile 128x16 -> transposed smem
#pragma unroll
        for (int p = 0; p < 2; ++p) {
            int fid = tid + p * 256;           // 0..511 float4s
            int row = fid >> 2;
            int kq  = (fid & 3) << 2;
            float4 a = *(const float4*)(Aptr + (size_t)row * K + k0 + kq);
            As[kq + 0][row] = a.x;
            As[kq + 1][row] = a.y;
            As[kq + 2][row] = a.z;
            As[kq + 3][row] = a.w;
        }
        // B tile 16x128 -> direct smem
#pragma unroll
        for (int p = 0; p < 2; ++p) {
            int fid  = tid + p * 256;
            int krow = fid >> 5;
            int nq   = (fid & 31) << 2;
            *(float4*)&Bs[krow][nq] =
                *(const float4*)(Bptr + (size_t)(k0 + krow) * N + nq);
        }
        __syncthreads();

#pragma unroll
        for (int k = 0; k < 16; ++k) {
            float a_frag[8], b_frag[8];
            *(float4*)&a_frag[0] = *(float4*)&As[k][ty * 4];
            *(float4*)&a_frag[4] = *(float4*)&As[k][ty * 4 + 64];
            *(float4*)&b_frag[0] = *(float4*)&Bs[k][tx * 4];
            *(float4*)&b_frag[4] = *(float4*)&Bs[k][tx * 4 + 64];
#pragma unroll
            for (int i = 0; i < 8; ++i)
#pragma unroll
                for (int j = 0; j < 8; ++j)
                    acc[i][j] = fmaf(a_frag[i], b_frag[j], acc[i][j]);
        }
        __syncthreads();
    }

    // epilogue
#pragma unroll
    for (int i = 0; i < 8; ++i) {
        int row = bm + ty * 4 + (i >> 2) * 64 + (i & 3);
#pragma unroll
        for (int jj = 0; jj < 2; ++jj) {
            int col = bn + tx * 4 + jj * 64;
            float4 r;
            r.x = acc[i][jj * 4 + 0];
            r.y = acc[i][jj * 4 + 1];
            r.z = acc[i][jj * 4 + 2];
            r.w = acc[i][jj * 4 + 3];
            if (BIAS) {
                float4 b4 = *(const float4*)(bias + col);
                r.x += b4.x; r.y += b4.y; r.z += b4.z; r.w += b4.w;
            }
            if (GELU) {
                r.x = gelu_exact(r.x); r.y = gelu_exact(r.y);
                r.z = gelu_exact(r.z); r.w = gelu_exact(r.w);
            }
            *(float4*)(C + (size_t)row * N + col) = r;
        }
    }
}

// ==================================================================
// Flash attention: per (b, h, 64-row q-block). Br=Bc=64, DH=64.
// Online softmax, P reuses the K smem buffer.
// Dynamic smem: Qs[64][64] + KPs[64][68] + Vs[64][64] = 50176 B
// ==================================================================
__global__ __launch_bounds__(256) void attn_kernel(
    const float* __restrict__ qkv, float* __restrict__ out)
{
    extern __shared__ float sm[];
    float (*Qs)[64]  = (float(*)[64]) sm;                         // Q[r][d]
    float (*KPs)[68] = (float(*)[68])(sm + 64 * 64);              // K[c][d] / P[r][c]
    float (*Vs)[64]  = (float(*)[64])(sm + 64 * 64 + 64 * 68);    // V[c][d]

    const int b  = blockIdx.z, h = blockIdx.y, qb = blockIdx.x;
    const int tid = threadIdx.x;
    const int tx = tid & 15, ty = tid >> 4;

    const size_t base = ((size_t)b * N_) * (3 * D_) + h * DH_;
    const float* qp = qkv + base;
    const float* kp = qkv + base + D_;
    const float* vp = qkv + base + 2 * D_;
    const int row0 = qb * 64;

    // load Q tile (64 x 64)
    for (int f = tid; f < 64 * 16; f += 256) {
        int r = f >> 4, dq = (f & 15) << 2;
        *(float4*)&Qs[r][dq] =
            *(const float4*)(qp + (size_t)(row0 + r) * (3 * D_) + dq);
    }

    float m_i[4], l_i[4], o[4][4];
#pragma unroll
    for (int i = 0; i < 4; ++i) {
        m_i[i] = -1e30f; l_i[i] = 0.f;
#pragma unroll
        for (int j = 0; j < 4; ++j) o[i][j] = 0.f;
    }

    for (int c0 = 0; c0 < N_; c0 += 64) {
        __syncthreads();   // prev-iter readers of KPs/Vs done (also covers Q store)
        for (int f = tid; f < 64 * 16; f += 256) {
            int r = f >> 4, dq = (f & 15) << 2;
            *(float4*)&KPs[r][dq] =
                *(const float4*)(kp + (size_t)(c0 + r) * (3 * D_) + dq);
            *(float4*)&Vs[r][dq] =
                *(const float4*)(vp + (size_t)(c0 + r) * (3 * D_) + dq);
        }
        __syncthreads();

        // S = Q K^T : rows i*16+ty, cols j*16+tx
        float s[4][4];
#pragma unroll
        for (int i = 0; i < 4; ++i)
#pragma unroll
            for (int j = 0; j < 4; ++j) s[i][j] = 0.f;

#pragma unroll
        for (int d = 0; d < 64; d += 4) {
            float4 q4[4], k4[4];
#pragma unroll
            for (int i = 0; i < 4; ++i) q4[i] = *(float4*)&Qs[i * 16 + ty][d];
#pragma unroll
            for (int j = 0; j < 4; ++j) k4[j] = *(float4*)&KPs[j * 16 + tx][d];
#pragma unroll
            for (int i = 0; i < 4; ++i)
#pragma unroll
                for (int j = 0; j < 4; ++j)
                    s[i][j] += q4[i].x * k4[j].x + q4[i].y * k4[j].y +
                               q4[i].z * k4[j].z + q4[i].w * k4[j].w;
        }

        // online softmax update (scale = DH^-0.5 = 0.125)
#pragma unroll
        for (int i = 0; i < 4; ++i) {
            float mt = -1e30f;
#pragma unroll
            for (int j = 0; j < 4; ++j) { s[i][j] *= 0.125f; mt = fmaxf(mt, s[i][j]); }
#pragma unroll
            for (int off = 8; off; off >>= 1)
                mt = fmaxf(mt, __shfl_xor_sync(0xffffffffu, mt, off, 16));
            float m_new = fmaxf(m_i[i], mt);
            float alpha = __expf(m_i[i] - m_new);
            float lsum = 0.f;
#pragma unroll
            for (int j = 0; j < 4; ++j) {
                float p = __expf(s[i][j] - m_new);
                s[i][j] = p;
                lsum += p;
            }
#pragma unroll
            for (int off = 8; off; off >>= 1)
                lsum += __shfl_xor_sync(0xffffffffu, lsum, off, 16);
            l_i[i] = l_i[i] * alpha + lsum;
            m_i[i] = m_new;
#pragma unroll
            for (int j = 0; j < 4; ++j) o[i][j] *= alpha;
        }

        __syncthreads();   // everyone done reading K before P overwrite
#pragma unroll
        for (int i = 0; i < 4; ++i)
#pragma unroll
            for (int j = 0; j < 4; ++j)
                KPs[i * 16 + ty][j * 16 + tx] = s[i][j];
        __syncthreads();

        // O += P V : O cols = tx*4..tx*4+3
#pragma unroll 8
        for (int c = 0; c < 64; ++c) {
            float4 v4 = *(float4*)&Vs[c][tx * 4];
#pragma unroll
            for (int i = 0; i < 4; ++i) {
                float p = KPs[i * 16 + ty][c];
                o[i][0] = fmaf(p, v4.x, o[i][0]);
                o[i][1] = fmaf(p, v4.y, o[i][1]);
                o[i][2] = fmaf(p, v4.z, o[i][2]);
                o[i][3] = fmaf(p, v4.w, o[i][3]);
            }
        }
    }

    // write out: [B, N, H*DH]
#pragma unroll
    for (int i = 0; i < 4; ++i) {
        float inv = 1.0f / l_i[i];
        float4 r;
        r.x = o[i][0] * inv; r.y = o[i][1] * inv;
        r.z = o[i][2] * inv; r.w = o[i][3] * inv;
        *(float4*)(out + ((size_t)b * N_ + row0 + i * 16 + ty) * D_ +
                   h * DH_ + tx * 4) = r;
    }
}

// ==================================================================
// Launch
// ==================================================================
extern "C" void kernel_launch(void* const* d_in, const int* in_sizes, int n_in,
                              void* d_out, int out_size)
{
    (void)in_sizes; (void)n_in; (void)out_size;
    const float* x     = (const float*)d_in[0];
    const float* ln1_g = (const float*)d_in[1];
    const float* ln1_b = (const float*)d_in[2];
    const float* w_qkv = (const float*)d_in[3];
    const float* w_out = (const float*)d_in[4];
    const float* b_out = (const float*)d_in[5];
    const float* ln2_g = (const float*)d_in[6];
    const float* ln2_b = (const float*)d_in[7];
    const float* w1    = (const float*)d_in[8];
    const float* b1    = (const float*)d_in[9];
    const float* w2    = (const float*)d_in[10];
    const float* b2    = (const float*)d_in[11];
    float* out = (float*)d_out;

    float *xn, *qkvb, *attn, *x2, *x2n, *hbuf;
    cudaGetSymbolAddress((void**)&xn,   g_xn);
    cudaGetSymbolAddress((void**)&qkvb, g_qkv);
    cudaGetSymbolAddress((void**)&attn, g_attn);
    cudaGetSymbolAddress((void**)&x2,   g_x2);
    cudaGetSymbolAddress((void**)&x2n,  g_x2n);
    cudaGetSymbolAddress((void**)&hbuf, g_h);

    const int ATTN_SMEM = (64 * 64 + 64 * 68 + 64 * 64) * 4;   // 50176 B
    cudaFuncSetAttribute(attn_kernel,
                         cudaFuncAttributeMaxDynamicSharedMemorySize, ATTN_SMEM);

    // 1. LN1
    ln_kernel<<<TOK, 256>>>(x, ln1_g, ln1_b, xn);
    // 2. QKV = xn @ w_qkv                       [8192,1024]x[1024,3072]
    sgemm_kernel<false, false><<<dim3(3 * D_ / 128, TOK / 128), 256>>>(
        xn, w_qkv, nullptr, qkvb, TOK, 3 * D_, D_);
    // 3. attention
    attn_kernel<<<dim3(N_ / 64, H_, B_), 256, ATTN_SMEM>>>(qkvb, attn);
    // 4. x2 = attn @ w_out + b_out              [8192,1024]x[1024,1024]
    sgemm_kernel<true, false><<<dim3(D_ / 128, TOK / 128), 256>>>(
        attn, w_out, b_out, x2, TOK, D_, D_);
    // 5. LN2
    ln_kernel<<<TOK, 256>>>(x2, ln2_g, ln2_b, x2n);
    // 6. h = gelu(x2n @ w1 + b1)                [8192,1024]x[1024,4096]
    sgemm_kernel<true, true><<<dim3(MLP_ / 128, TOK / 128), 256>>>(
        x2n, w1, b1, hbuf, TOK, MLP_, D_);
    // 7. out = h @ w2 + b2                      [8192,4096]x[4096,1024]
    sgemm_kernel<true, false><<<dim3(D_ / 128, TOK / 128), 256>>>(
        hbuf, w2, b2, out, TOK, D_, MLP_);
}

// round 3
// speedup vs baseline: 1.0006x; 1.0006x over previous
#include <cuda_runtime.h>
#include <math.h>

#define B_    8
#define N_    1024
#define D_    1024
#define H_    16
#define DH_   64
#define MLP_  4096
#define TOK   (B_ * N_)         // 8192 rows

// ---------------- scratch (no allocations allowed) ----------------
__device__ float g_xn  [TOK * D_];        // 32 MB
__device__ float g_qkv [TOK * 3 * D_];    // 96 MB
__device__ float g_attn[TOK * D_];        // 32 MB
__device__ float g_x2  [TOK * D_];        // 32 MB
__device__ float g_x2n [TOK * D_];        // 32 MB
__device__ float g_h   [TOK * MLP_];      // 128 MB

// ==================================================================
// LayerNorm: one block per row, D = 1024, 256 threads x float4
// ==================================================================
__global__ __launch_bounds__(256) void ln_kernel(
    const float* __restrict__ x, const float* __restrict__ g,
    const float* __restrict__ b, float* __restrict__ y)
{
    const int row  = blockIdx.x;
    const int tid  = threadIdx.x;
    const int lane = tid & 31, w = tid >> 5;
    const float* xr = x + (size_t)row * D_;

    float4 v = *(const float4*)(xr + tid * 4);
    float s  = v.x + v.y + v.z + v.w;
    float ss = fmaf(v.x, v.x, fmaf(v.y, v.y, fmaf(v.z, v.z, v.w * v.w)));
#pragma unroll
    for (int o = 16; o; o >>= 1) {
        s  += __shfl_xor_sync(0xffffffffu, s,  o);
        ss += __shfl_xor_sync(0xffffffffu, ss, o);
    }
    __shared__ float rs_[8], rss_[8];
    if (!lane) { rs_[w] = s; rss_[w] = ss; }
    __syncthreads();
    float S = 0.f, SS = 0.f;
#pragma unroll
    for (int i = 0; i < 8; ++i) { S += rs_[i]; SS += rss_[i]; }
    const float mu  = S * (1.0f / D_);
    const float var = SS * (1.0f / D_) - mu * mu;
    const float rstd = rsqrtf(var + 1e-5f);

    float4 gv = *(const float4*)(g + tid * 4);
    float4 bv = *(const float4*)(b + tid * 4);
    float4 o;
    o.x = (v.x - mu) * rstd * gv.x + bv.x;
    o.y = (v.y - mu) * rstd * gv.y + bv.y;
    o.z = (v.z - mu) * rstd * gv.z + bv.z;
    o.w = (v.w - mu) * rstd * gv.w + bv.w;
    *(float4*)(y + (size_t)row * D_ + tid * 4) = o;
}

// ==================================================================
// SGEMM: C[M,N] = A[M,K] @ B[K,N] (+bias)(+exact GELU)
// 128x128 tile, BK=16, 256 threads, 8x8 microtile (2x contiguous 4s)
// All dims are multiples of 128/16 in this problem: no bounds checks.
// ==================================================================
__device__ __forceinline__ float gelu_exact(float v)
{
    return 0.5f * v * (1.0f + erff(v * 0.70710678118654752f));
}

template <bool BIAS, bool GELU>
__global__ __launch_bounds__(256, 2) void sgemm_kernel(
    const float* __restrict__ A, const float* __restrict__ B,
    const float* __restrict__ bias, float* __restrict__ C,
    int M, int N, int K)
{
    const int bm = blockIdx.y * 128;
    const int bn = blockIdx.x * 128;
    const int tid = threadIdx.x;
    const int tx = tid & 15, ty = tid >> 4;

    __shared__ float As[16][132];   // transposed A tile, padded (2-way max on store)
    __shared__ float Bs[16][128];

    float acc[8][8];
#pragma unroll
    for (int i = 0; i < 8; ++i)
#pragma unroll
        for (int j = 0; j < 8; ++j) acc[i][j] = 0.f;

    const float* Aptr = A + (size_t)bm * K;
    const float* Bptr = B + bn;

    for (int k0 = 0; k0 < K; k0 += 16) {
        // A tile 128x16 -> transposed smem
#pragma unroll
        for (int p = 0; p < 2; ++p) {
            int fid = tid + p * 256;           // 0..511 float4s
            int row = fid >> 2;
            int kq  = (fid & 3) << 2;
            float4 a = *(const float4*)(Aptr + (size_t)row * K + k0 + kq);
            As[kq + 0][row] = a.x;
            As[kq + 1][row] = a.y;
            As[kq + 2][row] = a.z;
            As[kq + 3][row] = a.w;
        }
        // B tile 16x128 -> direct smem
#pragma unroll
        for (int p = 0; p < 2; ++p) {
            int fid  = tid + p * 256;
            int krow = fid >> 5;
            int nq   = (fid & 31) << 2;
            *(float4*)&Bs[krow][nq] =
                *(const float4*)(Bptr + (size_t)(k0 + krow) * N + nq);
        }
        __syncthreads();

#pragma unroll
        for (int k = 0; k < 16; ++k) {
            float a_frag[8], b_frag[8];
            *(float4*)&a_frag[0] = *(float4*)&As[k][ty * 4];
            *(float4*)&a_frag[4] = *(float4*)&As[k][ty * 4 + 64];
            *(float4*)&b_frag[0] = *(float4*)&Bs[k][tx * 4];
            *(float4*)&b_frag[4] = *(float4*)&Bs[k][tx * 4 + 64];
#pragma unroll
            for (int i = 0; i < 8; ++i)
#pragma unroll
                for (int j = 0; j < 8; ++j)
                    acc[i][j] = fmaf(a_frag[i], b_frag[j], acc[i][j]);
        }
        __syncthreads();
    }

    // epilogue
#pragma unroll
    for (int i = 0; i < 8; ++i) {
        int row = bm + ty * 4 + (i >> 2) * 64 + (i & 3);
#pragma unroll
        for (int jj = 0; jj < 2; ++jj) {
            int col = bn + tx * 4 + jj * 64;
            float4 r;
            r.x = acc[i][jj * 4 + 0];
            r.y = acc[i][jj * 4 + 1];
            r.z = acc[i][jj * 4 + 2];
            r.w = acc[i][jj * 4 + 3];
            if (BIAS) {
                float4 b4 = *(const float4*)(bias + col);
                r.x += b4.x; r.y += b4.y; r.z += b4.z; r.w += b4.w;
            }
            if (GELU) {
                r.x = gelu_exact(r.x); r.y = gelu_exact(r.y);
                r.z = gelu_exact(r.z); r.w = gelu_exact(r.w);
            }
            *(float4*)(C + (size_t)row * N + col) = r;
        }
    }
}

// ==================================================================
// Flash attention: per (b, h, 64-row q-block). Br=Bc=64, DH=64.
// Online softmax, P reuses the K smem buffer.
// Dynamic smem: Qs[64][64] + KPs[64][68] + Vs[64][64] = 50176 B
// ==================================================================
__global__ __launch_bounds__(256) void attn_kernel(
    const float* __restrict__ qkv, float* __restrict__ out)
{
    extern __shared__ float sm[];
    float (*Qs)[64]  = (float(*)[64]) sm;                         // Q[r][d]
    float (*KPs)[68] = (float(*)[68])(sm + 64 * 64);              // K[c][d] / P[r][c]
    float (*Vs)[64]  = (float(*)[64])(sm + 64 * 64 + 64 * 68);    // V[c][d]

    const int b  = blockIdx.z, h = blockIdx.y, qb = blockIdx.x;
    const int tid = threadIdx.x;
    const int tx = tid & 15, ty = tid >> 4;

    const size_t base = ((size_t)b * N_) * (3 * D_) + h * DH_;
    const float* qp = qkv + base;
    const float* kp = qkv + base + D_;
    const float* vp = qkv + base + 2 * D_;
    const int row0 = qb * 64;

    // load Q tile (64 x 64)
    for (int f = tid; f < 64 * 16; f += 256) {
        int r = f >> 4, dq = (f & 15) << 2;
        *(float4*)&Qs[r][dq] =
            *(const float4*)(qp + (size_t)(row0 + r) * (3 * D_) + dq);
    }

    float m_i[4], l_i[4], o[4][4];
#pragma unroll
    for (int i = 0; i < 4; ++i) {
        m_i[i] = -1e30f; l_i[i] = 0.f;
#pragma unroll
        for (int j = 0; j < 4; ++j) o[i][j] = 0.f;
    }

    for (int c0 = 0; c0 < N_; c0 += 64) {
        __syncthreads();   // prev-iter readers of KPs/Vs done (also covers Q store)
        for (int f = tid; f < 64 * 16; f += 256) {
            int r = f >> 4, dq = (f & 15) << 2;
            *(float4*)&KPs[r][dq] =
                *(const float4*)(kp + (size_t)(c0 + r) * (3 * D_) + dq);
            *(float4*)&Vs[r][dq] =
                *(const float4*)(vp + (size_t)(c0 + r) * (3 * D_) + dq);
        }
        __syncthreads();

        // S = Q K^T : rows i*16+ty, cols j*16+tx
        float s[4][4];
#pragma unroll
        for (int i = 0; i < 4; ++i)
#pragma unroll
            for (int j = 0; j < 4; ++j) s[i][j] = 0.f;

#pragma unroll
        for (int d = 0; d < 64; d += 4) {
            float4 q4[4], k4[4];
#pragma unroll
            for (int i = 0; i < 4; ++i) q4[i] = *(float4*)&Qs[i * 16 + ty][d];
#pragma unroll
            for (int j = 0; j < 4; ++j) k4[j] = *(float4*)&KPs[j * 16 + tx][d];
#pragma unroll
            for (int i = 0; i < 4; ++i)
#pragma unroll
                for (int j = 0; j < 4; ++j)
                    s[i][j] += q4[i].x * k4[j].x + q4[i].y * k4[j].y +
                               q4[i].z * k4[j].z + q4[i].w * k4[j].w;
        }

        // online softmax update (scale = DH^-0.5 = 0.125)
#pragma unroll
        for (int i = 0; i < 4; ++i) {
            float mt = -1e30f;
#pragma unroll
            for (int j = 0; j < 4; ++j) { s[i][j] *= 0.125f; mt = fmaxf(mt, s[i][j]); }
#pragma unroll
            for (int off = 8; off; off >>= 1)
                mt = fmaxf(mt, __shfl_xor_sync(0xffffffffu, mt, off, 16));
            float m_new = fmaxf(m_i[i], mt);
            float alpha = __expf(m_i[i] - m_new);
            float lsum = 0.f;
#pragma unroll
            for (int j = 0; j < 4; ++j) {
                float p = __expf(s[i][j] - m_new);
                s[i][j] = p;
                lsum += p;
            }
#pragma unroll
            for (int off = 8; off; off >>= 1)
                lsum += __shfl_xor_sync(0xffffffffu, lsum, off, 16);
            l_i[i] = l_i[i] * alpha + lsum;
            m_i[i] = m_new;
#pragma unroll
            for (int j = 0; j < 4; ++j) o[i][j] *= alpha;
        }

        __syncthreads();   // everyone done reading K before P overwrite
#pragma unroll
        for (int i = 0; i < 4; ++i)
#pragma unroll
            for (int j = 0; j < 4; ++j)
                KPs[i * 16 + ty][j * 16 + tx] = s[i][j];
        __syncthreads();

        // O += P V : O cols = tx*4..tx*4+3
#pragma unroll 8
        for (int c = 0; c < 64; ++c) {
            float4 v4 = *(float4*)&Vs[c][tx * 4];
#pragma unroll
            for (int i = 0; i < 4; ++i) {
                float p = KPs[i * 16 + ty][c];
                o[i][0] = fmaf(p, v4.x, o[i][0]);
                o[i][1] = fmaf(p, v4.y, o[i][1]);
                o[i][2] = fmaf(p, v4.z, o[i][2]);
                o[i][3] = fmaf(p, v4.w, o[i][3]);
            }
        }
    }

    // write out: [B, N, H*DH]
#pragma unroll
    for (int i = 0; i < 4; ++i) {
        float inv = 1.0f / l_i[i];
        float4 r;
        r.x = o[i][0] * inv; r.y = o[i][1] * inv;
        r.z = o[i][2] * inv; r.w = o[i][3] * inv;
        *(float4*)(out + ((size_t)b * N_ + row0 + i * 16 + ty) * D_ +
                   h * DH_ + tx * 4) = r;
    }
}

// ==================================================================
// Launch
// ==================================================================
extern "C" void kernel_launch(void* const* d_in, const int* in_sizes, int n_in,
                              void* d_out, int out_size)
{
    (void)in_sizes; (void)n_in; (void)out_size;
    const float* x     = (const float*)d_in[0];
    const float* ln1_g = (const float*)d_in[1];
    const float* ln1_b = (const float*)d_in[2];
    const float* w_qkv = (const float*)d_in[3];
    const float* w_out = (const float*)d_in[4];
    const float* b_out = (const float*)d_in[5];
    const float* ln2_g = (const float*)d_in[6];
    const float* ln2_b = (const float*)d_in[7];
    const float* w1    = (const float*)d_in[8];
    const float* b1    = (const float*)d_in[9];
    const float* w2    = (const float*)d_in[10];
    const float* b2    = (const float*)d_in[11];
    float* out = (float*)d_out;

    float *xn, *qkvb, *attn, *x2, *x2n, *hbuf;
    cudaGetSymbolAddress((void**)&xn,   g_xn);
    cudaGetSymbolAddress((void**)&qkvb, g_qkv);
    cudaGetSymbolAddress((void**)&attn, g_attn);
    cudaGetSymbolAddress((void**)&x2,   g_x2);
    cudaGetSymbolAddress((void**)&x2n,  g_x2n);
    cudaGetSymbolAddress((void**)&hbuf, g_h);

    const int ATTN_SMEM = (64 * 64 + 64 * 68 + 64 * 64) * 4;   // 50176 B
    cudaFuncSetAttribute(attn_kernel,
                         cudaFuncAttributeMaxDynamicSharedMemorySize, ATTN_SMEM);

    // 1. LN1
    ln_kernel<<<TOK, 256>>>(x, ln1_g, ln1_b, xn);
    // 2. QKV = xn @ w_qkv                       [8192,1024]x[1024,3072]
    sgemm_kernel<false, false><<<dim3(3 * D_ / 128, TOK / 128), 256>>>(
        xn, w_qkv, nullptr, qkvb, TOK, 3 * D_, D_);
    // 3. attention
    attn_kernel<<<dim3(N_ / 64, H_, B_), 256, ATTN_SMEM>>>(qkvb, attn);
    // 4. x2 = attn @ w_out + b_out              [8192,1024]x[1024,1024]
    sgemm_kernel<true, false><<<dim3(D_ / 128, TOK / 128), 256>>>(
        attn, w_out, b_out, x2, TOK, D_, D_);
    // 5. LN2
    ln_kernel<<<TOK, 256>>>(x2, ln2_g, ln2_b, x2n);
    // 6. h = gelu(x2n @ w1 + b1)                [8192,1024]x[1024,4096]
    sgemm_kernel<true, true><<<dim3(MLP_ / 128, TOK / 128), 256>>>(
        x2n, w1, b1, hbuf, TOK, MLP_, D_);
    // 7. out = h @ w2 + b2                      [8192,4096]x[4096,1024]
    sgemm_kernel<true, false><<<dim3(D_ / 128, TOK / 128), 256>>>(
        hbuf, w2, b2, out, TOK, D_, MLP_);
}